// round 11
// baseline (speedup 1.0000x reference)
#include <cuda_runtime.h>
#include <cuda_fp16.h>
#include <cstdint>
#include <math.h>

// GMM log-likelihood, single-pass fp16 HMMA (sm_100-safe: no tcgen05).
// lp[b,k] = const_k - 0.5 * || Lh_k xh_b - c_k ||^2 ; out[b] = logsumexp_k lp
//   c_k = Lh_k m_k (fp32, rounded-L consistent), const_k uses EXACT diag logdet.
// R10: 4-warp CTAs, each warp owns 32 m-rows (2 A-sets) -> each B ldmatrix
// feeds 8 MMAs (2x reuse), halving smem-crossbar traffic per MMA.
// cvt_l fused into prep_c. Still 2 CTAs/SM, comp-split grid 1024.

#define BATCH   65536
#define DIMS    128
#define NCOMP   16
#define MTILE   128
#define NTILES  (BATCH / MTILE)     // 512
#define NBLK    (NTILES * 2)        // 1024 (2 component-halves per tile)
#define KHALF   (NCOMP / 2)         // 8
#define THREADS 128

#define LOG2PI_TERM (-117.6241322501981f)   // -0.5 * 128 * log(2*pi)

// ------------------------- device scratch -------------------------
__device__ __half g_Xh[BATCH * DIMS];
__device__ __half g_Lh[NCOMP * DIMS * DIMS];
__device__ float  g_c[NCOMP * DIMS];
__device__ float  g_kc[NCOMP];
__device__ float  g_pm[2 * BATCH];   // partial running max
__device__ float  g_ps[2 * BATCH];   // partial running sum

// ------------------------- helpers -------------------------
__device__ __forceinline__ uint32_t smem_u32(const void* p) {
    uint32_t a;
    asm("{ .reg .u64 t; cvta.to.shared.u64 t, %1; cvt.u32.u64 %0, t; }"
        : "=r"(a) : "l"(p));
    return a;
}

// XOR swizzle: tile stored [128 rows][128 fp16], 256B/row, 16B chunks.
__device__ __forceinline__ uint32_t swz(int row, int c16) {
    int c = (c16 & 8) | ((c16 ^ row) & 7);
    return (uint32_t)(row * 256 + c * 16);
}

#define CP_COMMIT() asm volatile("cp.async.commit_group;" ::: "memory")
#define CP_WAIT0()  asm volatile("cp.async.wait_group 0;" ::: "memory")
#define CP_WAIT1()  asm volatile("cp.async.wait_group 1;" ::: "memory")

__device__ __forceinline__ void cp16(uint32_t dst, const void* src) {
    asm volatile("cp.async.cg.shared.global [%0], [%1], 16;"
                 :: "r"(dst), "l"(src) : "memory");
}

__device__ __forceinline__ void ldsm_x4(uint32_t* r, uint32_t addr) {
    asm volatile("ldmatrix.sync.aligned.m8n8.x4.shared.b16 {%0,%1,%2,%3}, [%4];"
                 : "=r"(r[0]), "=r"(r[1]), "=r"(r[2]), "=r"(r[3]) : "r"(addr));
}

#define MMA(c, a, b0_, b1_) \
    asm volatile("mma.sync.aligned.m16n8k16.row.col.f32.f16.f16.f32 " \
        "{%0,%1,%2,%3}, {%4,%5,%6,%7}, {%8,%9}, {%0,%1,%2,%3};" \
        : "+f"((c)[0]), "+f"((c)[1]), "+f"((c)[2]), "+f"((c)[3]) \
        : "r"((a)[0]), "r"((a)[1]), "r"((a)[2]), "r"((a)[3]), "r"(b0_), "r"(b1_))

// ------------------------- smem layout (dynamic) -------------------------
#define SM_XH  0u           // 32 KB
#define SM_LB  32768u       // + buf*32768, 2 buffers (32 KB each)
#define SM_C   98304u       // 16*128 fp32 = 8 KB
#define SM_K   106496u      // 16 fp32
#define SMEM_BYTES 106560

// ------------------------- tile loaders (128 threads) -------------------------
__device__ __forceinline__ void load_X_async(uint32_t sb, int m0) {
    const __half* src = g_Xh + (size_t)m0 * DIMS;
    int t = threadIdx.x;
    #pragma unroll
    for (int i = 0; i < 16; i++) {
        int c = t + i * 128;            // 16B-chunk id 0..2047
        int row = c >> 4, c16 = c & 15;
        cp16(sb + SM_XH + swz(row, c16), (const char*)src + row * 256 + c16 * 16);
    }
}

__device__ __forceinline__ void load_L_async(uint32_t sb, int buf, int comp) {
    const __half* src = g_Lh + (size_t)comp * DIMS * DIMS;
    uint32_t dst = sb + SM_LB + (uint32_t)buf * 32768u;
    int t = threadIdx.x;
    #pragma unroll
    for (int i = 0; i < 16; i++) {
        int c = t + i * 128;
        int row = c >> 4, c16 = c & 15;
        cp16(dst + swz(row, c16), (const char*)src + row * 256 + c16 * 16);
    }
}

// ------------------------- prep kernels -------------------------
__global__ void cvt_x_kernel(const float* __restrict__ x) {
    int i = blockIdx.x * blockDim.x + threadIdx.x;
    g_Xh[i] = __float2half(x[i]);
}

// Fused: convert L row to fp16 (writes g_Lh) + c_k = Lh_k m_k + logdet const.
__global__ void prep_cl_kernel(const float* __restrict__ p,
                               const float* __restrict__ m,
                               const float* __restrict__ lw) {
    int k = blockIdx.x;
    int i = threadIdx.x;
    const float* L  = p + (size_t)k * DIMS * DIMS + (size_t)i * DIMS;
    __half* Lh      = g_Lh + (size_t)k * DIMS * DIMS + (size_t)i * DIMS;
    const float* mk = m + (size_t)k * DIMS;
    float acc = 0.f;
    #pragma unroll 8
    for (int j = 0; j < DIMS; j++) {
        float v = L[j];
        __half h = __float2half(v);
        Lh[j] = h;
        acc = fmaf(__half2float(h), mk[j], acc);
    }
    g_c[k * DIMS + i] = acc;

    __shared__ float red[DIMS];
    red[i] = logf(L[i]);                    // EXACT diag p[k][i][i]
    __syncthreads();
    for (int st = DIMS / 2; st > 0; st >>= 1) {
        if (i < st) red[i] += red[i + st];
        __syncthreads();
    }
    if (i == 0) g_kc[k] = lw[k] + red[0] + LOG2PI_TERM;
}

// ------------------------- main kernel -------------------------
__global__ void __launch_bounds__(THREADS, 2) gmm_main() {
    extern __shared__ char smem[];
    uint32_t sb = smem_u32(smem);
    int tid  = threadIdx.x;
    int lane = tid & 31;
    int w    = tid >> 5;                // 0..3 ; warp owns m-rows [w*32, w*32+32)
    int tile = blockIdx.x >> 1;
    int ch   = blockIdx.x & 1;          // component half
    int base = ch * KHALF;
    int m0   = tile * MTILE;

    float* smC = (float*)(smem + SM_C);
    float* smK = (float*)(smem + SM_K);

    // prologue: group(X + L[base]) then group(L[base+1])
    load_X_async(sb, m0);
    load_L_async(sb, 0, base);
    CP_COMMIT();
    load_L_async(sb, 1, base + 1);
    CP_COMMIT();

    for (int i = tid; i < NCOMP * DIMS; i += THREADS) smC[i] = g_c[i];
    if (tid < NCOMP) smK[tid] = g_kc[tid];

    CP_WAIT1();
    __syncthreads();

    // Two A-sets resident (m-rows w*32.. and w*32+16..): 8 k16-chunks each
    uint32_t AH0[8][4], AH1[8][4];
    {
        int arow = w * 32 + ((lane >> 3) & 1) * 8 + (lane & 7);
        int achi = (lane >> 4) & 1;
        #pragma unroll
        for (int kc = 0; kc < 8; kc++) {
            ldsm_x4(AH0[kc], sb + SM_XH + swz(arow,      2 * kc + achi));
            ldsm_x4(AH1[kc], sb + SM_XH + swz(arow + 16, 2 * kc + achi));
        }
    }

    int g    = lane >> 2;
    int tig  = lane & 3;
    int brow = lane & 7;      // B ldmatrix row within n-tile
    int bci  = lane >> 3;     // B ldmatrix matrix index -> c16 offset

    float rm00 = -INFINITY, rm01 = -INFINITY, rm10 = -INFINITY, rm11 = -INFINITY;
    float rs00 = 0.f, rs01 = 0.f, rs10 = 0.f, rs11 = 0.f;

    for (int i = 0; i < KHALF; i++) {
        if (i > 0) {
            CP_WAIT0();               // L[base+i] resident
            __syncthreads();          // all warps done comp i-1 -> its buffer free
            if (i + 1 < KHALF) {
                load_L_async(sb, (i + 1) & 1, base + i + 1);
                CP_COMMIT();
            }
        }
        int kk = base + i;
        uint32_t Lh = sb + SM_LB + (uint32_t)(i & 1) * 32768u;

        float s00 = 0.f, s01 = 0.f, s10 = 0.f, s11 = 0.f;

        // B fragments double-buffered; prefetch j=0
        uint32_t bh0[2][4], bh1[2][4];
        ldsm_x4(bh0[0], Lh + swz(brow, bci));
        ldsm_x4(bh1[0], Lh + swz(64 + brow, bci));

        // n-tile pairs (nt, nt+8): 8 independent accumulator chains
        #pragma unroll 2
        for (int nt = 0; nt < 8; nt++) {
            float aE0[4] = {0.f, 0.f, 0.f, 0.f};   // mset0, n-tile nt, even k16
            float aO0[4] = {0.f, 0.f, 0.f, 0.f};   // mset0, n-tile nt, odd  k16
            float bE0[4] = {0.f, 0.f, 0.f, 0.f};   // mset0, n-tile nt+8
            float bO0[4] = {0.f, 0.f, 0.f, 0.f};
            float aE1[4] = {0.f, 0.f, 0.f, 0.f};   // mset1
            float aO1[4] = {0.f, 0.f, 0.f, 0.f};
            float bE1[4] = {0.f, 0.f, 0.f, 0.f};
            float bO1[4] = {0.f, 0.f, 0.f, 0.f};
            #pragma unroll
            for (int kcp = 0; kcp < 4; kcp++) {
                int j   = nt * 4 + kcp;
                int cur = j & 1, nxt = cur ^ 1;
                // prefetch B for j+1 (wraps harmlessly to (0,0) at the end)
                {
                    int jn   = j + 1;
                    int ntn  = (jn >> 2) & 7;
                    int kcpn = jn & 3;
                    ldsm_x4(bh0[nxt], Lh + swz(ntn * 8 + brow,      4 * kcpn + bci));
                    ldsm_x4(bh1[nxt], Lh + swz(ntn * 8 + 64 + brow, 4 * kcpn + bci));
                }
                // 8 MMAs per 2 ldsm.x4: B reused across both m-sets
                MMA(aE0, AH0[2 * kcp],     bh0[cur][0], bh0[cur][1]);
                MMA(aO0, AH0[2 * kcp + 1], bh0[cur][2], bh0[cur][3]);
                MMA(bE0, AH0[2 * kcp],     bh1[cur][0], bh1[cur][1]);
                MMA(bO0, AH0[2 * kcp + 1], bh1[cur][2], bh1[cur][3]);
                MMA(aE1, AH1[2 * kcp],     bh0[cur][0], bh0[cur][1]);
                MMA(aO1, AH1[2 * kcp + 1], bh0[cur][2], bh0[cur][3]);
                MMA(bE1, AH1[2 * kcp],     bh1[cur][0], bh1[cur][1]);
                MMA(bO1, AH1[2 * kcp + 1], bh1[cur][2], bh1[cur][3]);
            }
            // epilogue: smC values shared by both m-sets (same n columns)
            float ca0 = smC[kk * DIMS + nt * 8 + 2 * tig];
            float cb0 = smC[kk * DIMS + nt * 8 + 2 * tig + 1];
            float ca1 = smC[kk * DIMS + nt * 8 + 64 + 2 * tig];
            float cb1 = smC[kk * DIMS + nt * 8 + 64 + 2 * tig + 1];
            float y;
            y = aE0[0] + aO0[0] - ca0; s00 = fmaf(y, y, s00);
            y = aE0[1] + aO0[1] - cb0; s00 = fmaf(y, y, s00);
            y = aE0[2] + aO0[2] - ca0; s01 = fmaf(y, y, s01);
            y = aE0[3] + aO0[3] - cb0; s01 = fmaf(y, y, s01);
            y = bE0[0] + bO0[0] - ca1; s00 = fmaf(y, y, s00);
            y = bE0[1] + bO0[1] - cb1; s00 = fmaf(y, y, s00);
            y = bE0[2] + bO0[2] - ca1; s01 = fmaf(y, y, s01);
            y = bE0[3] + bO0[3] - cb1; s01 = fmaf(y, y, s01);
            y = aE1[0] + aO1[0] - ca0; s10 = fmaf(y, y, s10);
            y = aE1[1] + aO1[1] - cb0; s10 = fmaf(y, y, s10);
            y = aE1[2] + aO1[2] - ca0; s11 = fmaf(y, y, s11);
            y = aE1[3] + aO1[3] - cb0; s11 = fmaf(y, y, s11);
            y = bE1[0] + bO1[0] - ca1; s10 = fmaf(y, y, s10);
            y = bE1[1] + bO1[1] - cb1; s10 = fmaf(y, y, s10);
            y = bE1[2] + bO1[2] - ca1; s11 = fmaf(y, y, s11);
            y = bE1[3] + bO1[3] - cb1; s11 = fmaf(y, y, s11);
        }
        // reduce over the 4 threads of each quad (columns)
        s00 += __shfl_xor_sync(0xFFFFFFFFu, s00, 1);
        s00 += __shfl_xor_sync(0xFFFFFFFFu, s00, 2);
        s01 += __shfl_xor_sync(0xFFFFFFFFu, s01, 1);
        s01 += __shfl_xor_sync(0xFFFFFFFFu, s01, 2);
        s10 += __shfl_xor_sync(0xFFFFFFFFu, s10, 1);
        s10 += __shfl_xor_sync(0xFFFFFFFFu, s10, 2);
        s11 += __shfl_xor_sync(0xFFFFFFFFu, s11, 1);
        s11 += __shfl_xor_sync(0xFFFFFFFFu, s11, 2);

        float kc_ = smK[kk];
        float lp;
        lp = kc_ - 0.5f * s00;
        if (lp > rm00) { rs00 = rs00 * __expf(rm00 - lp) + 1.f; rm00 = lp; }
        else           { rs00 += __expf(lp - rm00); }
        lp = kc_ - 0.5f * s01;
        if (lp > rm01) { rs01 = rs01 * __expf(rm01 - lp) + 1.f; rm01 = lp; }
        else           { rs01 += __expf(lp - rm01); }
        lp = kc_ - 0.5f * s10;
        if (lp > rm10) { rs10 = rs10 * __expf(rm10 - lp) + 1.f; rm10 = lp; }
        else           { rs10 += __expf(lp - rm10); }
        lp = kc_ - 0.5f * s11;
        if (lp > rm11) { rs11 = rs11 * __expf(rm11 - lp) + 1.f; rm11 = lp; }
        else           { rs11 += __expf(lp - rm11); }
    }

    if (tig == 0) {
        int r0 = m0 + w * 32 + g;
        g_pm[ch * BATCH + r0]      = rm00;
        g_ps[ch * BATCH + r0]      = rs00;
        g_pm[ch * BATCH + r0 + 8]  = rm01;
        g_ps[ch * BATCH + r0 + 8]  = rs01;
        g_pm[ch * BATCH + r0 + 16] = rm10;
        g_ps[ch * BATCH + r0 + 16] = rs10;
        g_pm[ch * BATCH + r0 + 24] = rm11;
        g_ps[ch * BATCH + r0 + 24] = rs11;
    }
}

// ------------------------- combine kernel -------------------------
__global__ void combine_kernel(float* __restrict__ out) {
    int b = blockIdx.x * blockDim.x + threadIdx.x;
    float m0 = g_pm[b],         s0 = g_ps[b];
    float m1 = g_pm[BATCH + b], s1 = g_ps[BATCH + b];
    float M  = fmaxf(m0, m1);
    out[b] = M + logf(s0 * __expf(m0 - M) + s1 * __expf(m1 - M));
}

// ------------------------- launch -------------------------
extern "C" void kernel_launch(void* const* d_in, const int* in_sizes, int n_in,
                              void* d_out, int out_size) {
    const float* x     = (const float*)d_in[0];
    const float* means = (const float*)d_in[1];
    const float* prec  = (const float*)d_in[2];
    const float* logw  = (const float*)d_in[3];
    float* out = (float*)d_out;

    cudaFuncSetAttribute(gmm_main,
                         cudaFuncAttributeMaxDynamicSharedMemorySize, SMEM_BYTES);

    cvt_x_kernel<<<(BATCH * DIMS) / 256, 256>>>(x);
    prep_cl_kernel<<<NCOMP, DIMS>>>(prec, means, logw);
    gmm_main<<<NBLK, THREADS, SMEM_BYTES>>>();
    combine_kernel<<<BATCH / 256, 256>>>(out);
}

// round 13
// speedup vs baseline: 1.0903x; 1.0903x over previous
#include <cuda_runtime.h>
#include <cuda_fp16.h>
#include <cstdint>
#include <math.h>

// GMM log-likelihood, single-pass fp16 HMMA (sm_100-safe: no tcgen05).
// lp[b,k] = const_k - 0.5 * || Lh_k xh_b - c_k ||^2 ; out[b] = logsumexp_k lp
//   c_k = Lh_k m_k (fp32, rounded-L consistent), const_k uses EXACT diag logdet.
// R11 resubmitted after R12 infra failure: deferred logsumexp via smem stash,
// precomputed B-address column offsets (1 IADD per ldsm), comp-local smC/smK,
// vectorized cvt_x.

#define BATCH   65536
#define DIMS    128
#define NCOMP   16
#define MTILE   128
#define NTILES  (BATCH / MTILE)     // 512
#define NBLK    (NTILES * 2)        // 1024 (2 component-halves per tile)
#define KHALF   (NCOMP / 2)         // 8
#define THREADS 256

#define LOG2PI_TERM (-117.6241322501981f)   // -0.5 * 128 * log(2*pi)

// ------------------------- device scratch -------------------------
__device__ __half g_Xh[BATCH * DIMS];
__device__ __half g_Lh[NCOMP * DIMS * DIMS];
__device__ float  g_c[NCOMP * DIMS];
__device__ float  g_kc[NCOMP];
__device__ float  g_pm[2 * BATCH];   // partial running max
__device__ float  g_ps[2 * BATCH];   // partial running sum

// ------------------------- helpers -------------------------
__device__ __forceinline__ uint32_t smem_u32(const void* p) {
    uint32_t a;
    asm("{ .reg .u64 t; cvta.to.shared.u64 t, %1; cvt.u32.u64 %0, t; }"
        : "=r"(a) : "l"(p));
    return a;
}

// XOR swizzle: tile stored [128 rows][128 fp16], 256B/row, 16B chunks.
__device__ __forceinline__ uint32_t swz(int row, int c16) {
    int c = (c16 & 8) | ((c16 ^ row) & 7);
    return (uint32_t)(row * 256 + c * 16);
}

#define CP_COMMIT() asm volatile("cp.async.commit_group;" ::: "memory")
#define CP_WAIT0()  asm volatile("cp.async.wait_group 0;" ::: "memory")
#define CP_WAIT1()  asm volatile("cp.async.wait_group 1;" ::: "memory")

__device__ __forceinline__ void cp16(uint32_t dst, const void* src) {
    asm volatile("cp.async.cg.shared.global [%0], [%1], 16;"
                 :: "r"(dst), "l"(src) : "memory");
}

__device__ __forceinline__ void ldsm_x4(uint32_t* r, uint32_t addr) {
    asm volatile("ldmatrix.sync.aligned.m8n8.x4.shared.b16 {%0,%1,%2,%3}, [%4];"
                 : "=r"(r[0]), "=r"(r[1]), "=r"(r[2]), "=r"(r[3]) : "r"(addr));
}

#define MMA(c, a, b0_, b1_) \
    asm volatile("mma.sync.aligned.m16n8k16.row.col.f32.f16.f16.f32 " \
        "{%0,%1,%2,%3}, {%4,%5,%6,%7}, {%8,%9}, {%0,%1,%2,%3};" \
        : "+f"((c)[0]), "+f"((c)[1]), "+f"((c)[2]), "+f"((c)[3]) \
        : "r"((a)[0]), "r"((a)[1]), "r"((a)[2]), "r"((a)[3]), "r"(b0_), "r"(b1_))

// ------------------------- smem layout (dynamic) -------------------------
#define SM_XH  0u           // 32 KB
#define SM_LB  32768u       // + buf*32768, 2 buffers (32 KB each)
#define SM_C   98304u       // 8*128 fp32 = 4 KB (this CTA's comp-half only)
#define SM_K   102400u      // 8 fp32 (+pad to 64B)
#define SM_S   102464u      // stash: 8 warps x 8 g x 8 comps x 2 fp32 = 4 KB
#define SMEM_BYTES 106560

// ------------------------- tile loaders -------------------------
__device__ __forceinline__ void load_X_async(uint32_t sb, int m0) {
    const __half* src = g_Xh + (size_t)m0 * DIMS;
    int t = threadIdx.x;
    #pragma unroll
    for (int i = 0; i < 8; i++) {
        int c = t + i * 256;            // 16B-chunk id 0..2047
        int row = c >> 4, c16 = c & 15;
        cp16(sb + SM_XH + swz(row, c16), (const char*)src + row * 256 + c16 * 16);
    }
}

__device__ __forceinline__ void load_L_async(uint32_t sb, int buf, int comp) {
    const __half* src = g_Lh + (size_t)comp * DIMS * DIMS;
    uint32_t dst = sb + SM_LB + (uint32_t)buf * 32768u;
    int t = threadIdx.x;
    #pragma unroll
    for (int i = 0; i < 8; i++) {
        int c = t + i * 256;
        int row = c >> 4, c16 = c & 15;
        cp16(dst + swz(row, c16), (const char*)src + row * 256 + c16 * 16);
    }
}

// ------------------------- prep kernels -------------------------
__global__ void cvt_x_kernel(const float4* __restrict__ x) {
    int i = blockIdx.x * blockDim.x + threadIdx.x;   // 4 floats per thread
    float4 v = x[i];
    __half2* dst = (__half2*)g_Xh;
    dst[2 * i]     = __floats2half2_rn(v.x, v.y);
    dst[2 * i + 1] = __floats2half2_rn(v.z, v.w);
}

// Fused: convert L row to fp16 (writes g_Lh) + c_k = Lh_k m_k + logdet const.
__global__ void prep_cl_kernel(const float* __restrict__ p,
                               const float* __restrict__ m,
                               const float* __restrict__ lw) {
    int k = blockIdx.x;
    int i = threadIdx.x;
    const float* L  = p + (size_t)k * DIMS * DIMS + (size_t)i * DIMS;
    __half* Lh      = g_Lh + (size_t)k * DIMS * DIMS + (size_t)i * DIMS;
    const float* mk = m + (size_t)k * DIMS;
    float acc = 0.f;
    #pragma unroll 8
    for (int j = 0; j < DIMS; j++) {
        __half h = __float2half(L[j]);
        Lh[j] = h;
        acc = fmaf(__half2float(h), mk[j], acc);
    }
    g_c[k * DIMS + i] = acc;

    __shared__ float red[DIMS];
    red[i] = logf(L[i]);                    // EXACT diag p[k][i][i]
    __syncthreads();
    for (int st = DIMS / 2; st > 0; st >>= 1) {
        if (i < st) red[i] += red[i + st];
        __syncthreads();
    }
    if (i == 0) g_kc[k] = lw[k] + red[0] + LOG2PI_TERM;
}

// ------------------------- main kernel -------------------------
__global__ void __launch_bounds__(THREADS, 2) gmm_main() {
    extern __shared__ char smem[];
    uint32_t sb = smem_u32(smem);
    int tid  = threadIdx.x;
    int lane = tid & 31;
    int w    = tid >> 5;
    int tile = blockIdx.x >> 1;
    int ch   = blockIdx.x & 1;          // component half
    int base = ch * KHALF;
    int m0   = tile * MTILE;

    float* smC = (float*)(smem + SM_C);
    float* smK = (float*)(smem + SM_K);
    float* smS = (float*)(smem + SM_S);

    // prologue: group(X + L[base]) then group(L[base+1])
    load_X_async(sb, m0);
    load_L_async(sb, 0, base);
    CP_COMMIT();
    load_L_async(sb, 1, base + 1);
    CP_COMMIT();

    // comp-local constants only (8 comps)
    for (int i = tid; i < KHALF * DIMS; i += THREADS)
        smC[i] = g_c[base * DIMS + i];
    if (tid < KHALF) smK[tid] = g_kc[base + tid];

    CP_WAIT1();
    __syncthreads();

    // A fragments (Xh) resident: 8 k16-chunks
    uint32_t AH[8][4];
    {
        int arow = w * 16 + ((lane >> 3) & 1) * 8 + (lane & 7);
        int achi = (lane >> 4) & 1;
        #pragma unroll
        for (int kc = 0; kc < 8; kc++)
            ldsm_x4(AH[kc], sb + SM_XH + swz(arow, 2 * kc + achi));
    }

    int g    = lane >> 2;
    int tig  = lane & 3;
    int brow = lane & 7;      // B ldmatrix row within n-tile
    int bci  = lane >> 3;     // B ldmatrix matrix index (0..3) -> c16 low bits

    // Precomputed swizzle column offsets: addr = Lbase + brow*256 + nt*2048
    //                                          (+16384 for n+64) + colofs[kcp]
    uint32_t colofs[4];
    #pragma unroll
    for (int kcp = 0; kcp < 4; kcp++)
        colofs[kcp] = (uint32_t)((((kcp & 2) << 2) |
                                  (((((kcp & 1) << 2) | bci)) ^ brow)) << 4);
    uint32_t rowb = (uint32_t)(brow * 256);

    int stash = (w * 8 + g) * (2 * KHALF);   // smS base for this (warp,row-group)

    for (int i = 0; i < KHALF; i++) {
        if (i > 0) {
            CP_WAIT0();               // L[base+i] resident
            __syncthreads();          // all warps done comp i-1 -> its buffer free
            if (i + 1 < KHALF) {
                load_L_async(sb, (i + 1) & 1, base + i + 1);
                CP_COMMIT();
            }
        }
        uint32_t Lb = sb + SM_LB + (uint32_t)(i & 1) * 32768u + rowb;

        float s0 = 0.f, s1 = 0.f;

        // B fragments double-buffered; prefetch j=0
        uint32_t bh0[2][4], bh1[2][4];
        ldsm_x4(bh0[0], Lb + colofs[0]);
        ldsm_x4(bh1[0], Lb + 16384u + colofs[0]);

        // n-tile pairs (nt, nt+8): 4 independent accumulator chains
        #pragma unroll 2
        for (int nt = 0; nt < 8; nt++) {
            float accA0[4] = {0.f, 0.f, 0.f, 0.f};
            float accB0[4] = {0.f, 0.f, 0.f, 0.f};
            float accA1[4] = {0.f, 0.f, 0.f, 0.f};
            float accB1[4] = {0.f, 0.f, 0.f, 0.f};
            #pragma unroll
            for (int kcp = 0; kcp < 4; kcp++) {
                int j   = nt * 4 + kcp;
                int cur = j & 1, nxt = cur ^ 1;
                // prefetch B for j+1 (wraps harmlessly to (0,0) at the end)
                {
                    int jn   = j + 1;
                    int ntn  = (jn >> 2) & 7;
                    int kcpn = jn & 3;
                    uint32_t o = (uint32_t)(ntn * 2048) + colofs[kcpn];
                    ldsm_x4(bh0[nxt], Lb + o);
                    ldsm_x4(bh1[nxt], Lb + 16384u + o);
                }
                // 4 MMAs, 4 independent chains
                MMA(accA0, AH[2 * kcp],     bh0[cur][0], bh0[cur][1]);
                MMA(accB0, AH[2 * kcp + 1], bh0[cur][2], bh0[cur][3]);
                MMA(accA1, AH[2 * kcp],     bh1[cur][0], bh1[cur][1]);
                MMA(accB1, AH[2 * kcp + 1], bh1[cur][2], bh1[cur][3]);
            }
            float ca0 = smC[i * DIMS + nt * 8 + 2 * tig];
            float cb0 = smC[i * DIMS + nt * 8 + 2 * tig + 1];
            float ca1 = smC[i * DIMS + nt * 8 + 64 + 2 * tig];
            float cb1 = smC[i * DIMS + nt * 8 + 64 + 2 * tig + 1];
            float y;
            y = accA0[0] + accB0[0] - ca0; s0 = fmaf(y, y, s0);
            y = accA0[1] + accB0[1] - cb0; s0 = fmaf(y, y, s0);
            y = accA0[2] + accB0[2] - ca0; s1 = fmaf(y, y, s1);
            y = accA0[3] + accB0[3] - cb0; s1 = fmaf(y, y, s1);
            y = accA1[0] + accB1[0] - ca1; s0 = fmaf(y, y, s0);
            y = accA1[1] + accB1[1] - cb1; s0 = fmaf(y, y, s0);
            y = accA1[2] + accB1[2] - ca1; s1 = fmaf(y, y, s1);
            y = accA1[3] + accB1[3] - cb1; s1 = fmaf(y, y, s1);
        }
        // reduce over the 4 threads of each quad (columns)
        s0 += __shfl_xor_sync(0xFFFFFFFFu, s0, 1);
        s0 += __shfl_xor_sync(0xFFFFFFFFu, s0, 2);
        s1 += __shfl_xor_sync(0xFFFFFFFFu, s1, 1);
        s1 += __shfl_xor_sync(0xFFFFFFFFu, s1, 2);

        // stash; logsumexp fully deferred (same thread reads back later)
        if (tig == 0) {
            smS[stash + 2 * i]     = s0;
            smS[stash + 2 * i + 1] = s1;
        }
    }

    // ---- deferred logsumexp (tig==0 threads only; same-thread smem RAW) ----
    if (tig == 0) {
        float rm0 = -INFINITY, rm1 = -INFINITY, rs0 = 0.f, rs1 = 0.f;
        #pragma unroll
        for (int i = 0; i < KHALF; i++) {
            float kc_ = smK[i];
            float lp0 = kc_ - 0.5f * smS[stash + 2 * i];
            float lp1 = kc_ - 0.5f * smS[stash + 2 * i + 1];
            if (lp0 > rm0) { rs0 = rs0 * __expf(rm0 - lp0) + 1.f; rm0 = lp0; }
            else           { rs0 += __expf(lp0 - rm0); }
            if (lp1 > rm1) { rs1 = rs1 * __expf(rm1 - lp1) + 1.f; rm1 = lp1; }
            else           { rs1 += __expf(lp1 - rm1); }
        }
        int r0 = m0 + w * 16 + g;
        g_pm[ch * BATCH + r0]     = rm0;
        g_ps[ch * BATCH + r0]     = rs0;
        g_pm[ch * BATCH + r0 + 8] = rm1;
        g_ps[ch * BATCH + r0 + 8] = rs1;
    }
}

// ------------------------- combine kernel -------------------------
__global__ void combine_kernel(float* __restrict__ out) {
    int b = blockIdx.x * blockDim.x + threadIdx.x;
    float m0 = g_pm[b],         s0 = g_ps[b];
    float m1 = g_pm[BATCH + b], s1 = g_ps[BATCH + b];
    float M  = fmaxf(m0, m1);
    out[b] = M + logf(s0 * __expf(m0 - M) + s1 * __expf(m1 - M));
}

// ------------------------- launch -------------------------
extern "C" void kernel_launch(void* const* d_in, const int* in_sizes, int n_in,
                              void* d_out, int out_size) {
    const float* x     = (const float*)d_in[0];
    const float* means = (const float*)d_in[1];
    const float* prec  = (const float*)d_in[2];
    const float* logw  = (const float*)d_in[3];
    float* out = (float*)d_out;

    cudaFuncSetAttribute(gmm_main,
                         cudaFuncAttributeMaxDynamicSharedMemorySize, SMEM_BYTES);

    cvt_x_kernel<<<(BATCH * DIMS / 4) / 256, 256>>>((const float4*)x);
    prep_cl_kernel<<<NCOMP, DIMS>>>(prec, means, logw);
    gmm_main<<<NBLK, THREADS, SMEM_BYTES>>>();
    combine_kernel<<<BATCH / 256, 256>>>(out);
}